// round 12
// baseline (speedup 1.0000x reference)
#include <cuda_runtime.h>
#include <math.h>

// Reference reduces to: x0 = exp(-50*((X-.5)^2+(Y-.5)^2)); 100x { x = 0.25*Mask1*(N+S+E+W) }
// (down-sweep / coarse solve / up-sweep are dead code w.r.t. the returned value)
//
// Persistent kernel: 128 CTAs (1/SM, single wave), 10 super-steps x 10 smem-resident
// steps; halo exchange via ping-pong global buffers + epoch grid barrier.
// Software-pipelined step body: rows 1,2 of each stack (register-only dataflow) are
// computed BEFORE the per-step barrier, hiding barrier skew; rows 0,3 (need smem
// uu/dd) after. Edge lanes patch rows 1,2 horizontals from smem post-barrier.

#define H 1024
#define NT 100
#define TSTEPS 10
#define NSS (NT / TSTEPS)               // 10 super-steps
#define TILE_W 128
#define TILE_H 64
#define HALO TSTEPS                     // 10
#define EXW (TILE_W + 2 * HALO)         // 148
#define EXH (TILE_H + 2 * HALO)         // 84
#define PITCH 148
#define GPR 37
#define NBANDS (EXH / 4)                // 21
#define NSTACKS (NBANDS * GPR)          // 777
#define NTHREADS 896                    // 28 warps; regs/thread cap ~72
#define ACT_WARPS ((NSTACKS + 31) / 32) // 25
#define ACT_THREADS (ACT_WARPS * 32)    // 800
#define GRID_X (H / TILE_W)             // 8
#define GRID_Y (H / TILE_H)             // 16
#define NCTA (GRID_X * GRID_Y)          // 128
#define SMEM_FLOATS (EXH * PITCH)       // 12432
#define SMEM_BYTES (2 * SMEM_FLOATS * 4)  // 99456 B -> 1 CTA/SM

typedef unsigned long long u64;

__device__ float g_buf0[H * H];
__device__ float g_buf1[H * H];
__device__ volatile unsigned g_arr[NCTA];   // zero-init; epochs, monotone across replays
__device__ volatile unsigned g_go;

__device__ __forceinline__ u64 addx2(u64 a, u64 b) {
    u64 r; asm("add.rn.f32x2 %0,%1,%2;" : "=l"(r) : "l"(a), "l"(b)); return r;
}
__device__ __forceinline__ u64 mulx2(u64 a, u64 b) {
    u64 r; asm("mul.rn.f32x2 %0,%1,%2;" : "=l"(r) : "l"(a), "l"(b)); return r;
}
__device__ __forceinline__ u64 pk(float lo, float hi) {
    u64 r; asm("mov.b64 %0,{%1,%2};" : "=l"(r) : "f"(lo), "f"(hi)); return r;
}
__device__ __forceinline__ void unpk(u64 a, float& lo, float& hi) {
    asm("mov.b64 {%0,%1},%2;" : "=f"(lo), "=f"(hi) : "l"(a));
}

// Named barrier for the 25 active warps only (barrier id 1).
__device__ __forceinline__ void act_barrier() {
    asm volatile("bar.sync 1, %0;" :: "n"(ACT_THREADS) : "memory");
}

// Epoch grid barrier. All 128 CTAs co-resident (1 CTA/SM, grid < SM count).
__device__ __forceinline__ void grid_barrier(int bid, unsigned ep) {
    __syncthreads();
    if (threadIdx.x == 0) {
        __threadfence();
        g_arr[bid] = ep;
    }
    if (bid == 0) {
        if (threadIdx.x < NCTA) {
            while (g_arr[threadIdx.x] < ep) __nanosleep(32);
        }
        __syncthreads();
        if (threadIdx.x == 0) { __threadfence(); g_go = ep; }
    }
    if (threadIdx.x == 0) {
        while (g_go < ep) __nanosleep(32);
        __threadfence();
    }
    __syncthreads();
}

__global__ void __launch_bounds__(NTHREADS, 1)
jacobi_persist(const float* __restrict__ X, const float* __restrict__ Y,
               const float* __restrict__ mask, float* __restrict__ out) {
    extern __shared__ float smem[];
    float* xs0 = smem;
    float* xs1 = smem + SMEM_FLOATS;

    const int bx = blockIdx.x, by = blockIdx.y;
    const int bid = by * GRID_X + bx;
    const int r0b = by * TILE_H - HALO;
    const int c0  = bx * TILE_W - HALO;
    const int tid = threadIdx.x;
    const int lane = tid & 31;
    const int wid = tid >> 5;

    const unsigned ep0 = g_arr[0];   // equal across CTAs at launch start

    // Initial fill: x0 = exp(-50*((X-.5)^2+(Y-.5)^2)), zero outside domain.
    for (int i = tid; i < SMEM_FLOATS; i += NTHREADS) {
        int r = i / PITCH;
        int c = i - r * PITCH;
        int gr = r0b + r;
        int gc = c0 + c;
        float v = 0.f;
        if ((unsigned)gr < (unsigned)H && (unsigned)gc < (unsigned)H) {
            int g = gr * H + gc;
            float dx = X[g] - 0.5f;
            float dy = Y[g] - 0.5f;
            v = expf(-50.0f * (dx * dx + dy * dy));
        }
        xs0[i] = v;
    }

    const bool act = tid < NSTACKS;
    int band = tid / GPR;
    int cg   = tid - band * GPR;
    if (!act) { band = NBANDS - 1; cg = GPR - 1; }   // clamp: valid addrs, no stores
    const int r0 = band * 4;
    const int o0 = r0 * PITCH + 4 * cg;
    const bool has_up = (band > 0);
    const bool has_dn = (band < NBANDS - 1);

    // rc[i] at step s  <=>  s <= lim[i]
    int lim[4];
    #pragma unroll
    for (int i = 0; i < 4; i++) {
        int r = r0 + i;
        int m2 = (EXH - 1) - r;
        lim[i] = act ? (r < m2 ? r : m2) : 0;
    }

    // Premultiplied mask into packed registers (bounds-checked, zero outside).
    u64 m01[4], m23[4];
    #pragma unroll
    for (int i = 0; i < 4; i++) {
        float a = 0.f, b = 0.f, c = 0.f, d = 0.f;
        int gr = r0b + r0 + i;
        if (act && (unsigned)gr < (unsigned)H) {
            const float* mrow = mask + gr * H;
            int gc = c0 + 4 * cg;
            if ((unsigned)gc       < (unsigned)H) a = 0.25f * mrow[gc];
            if ((unsigned)(gc + 1) < (unsigned)H) b = 0.25f * mrow[gc + 1];
            if ((unsigned)(gc + 2) < (unsigned)H) c = 0.25f * mrow[gc + 2];
            if ((unsigned)(gc + 3) < (unsigned)H) d = 0.25f * mrow[gc + 3];
        }
        m01[i] = pk(a, b);
        m23[i] = pk(c, d);
    }
    __syncthreads();

    // Center values into packed registers.
    u64 c01[4], c23[4];
    #pragma unroll
    for (int i = 0; i < 4; i++) {
        ulonglong2 v = *(const ulonglong2*)(xs0 + o0 + i * PITCH);
        c01[i] = v.x;
        c23[i] = v.y;
    }

    #pragma unroll 1
    for (int ss = 0; ss < NSS; ss++) {
        // ---- 10 smem-resident steps, software-pipelined across the barrier.
        //      Ends with step-10 data in xs0 (10 swaps). ----
        if (wid < ACT_WARPS) {
            float* cur = xs0;
            float* nxt = xs1;
            #pragma unroll
            for (int s = 1; s <= TSTEPS; s++) {
                const bool rc0 = s <= lim[0];
                const bool rc1 = s <= lim[1];
                const bool rc2 = s <= lim[2];
                const bool rc3 = s <= lim[3];

                // ===== pre-barrier: rows 1,2 (register-only dataflow) =====
                float c1x, c1y, c1z, c1w, c2x, c2y, c2z, c2w;
                unpk(c01[1], c1x, c1y); unpk(c23[1], c1z, c1w);
                unpk(c01[2], c2x, c2y); unpk(c23[2], c2z, c2w);
                float l1 = __shfl_up_sync(0xffffffffu, c1w, 1);
                float r1 = __shfl_down_sync(0xffffffffu, c1x, 1);
                float l2 = __shfl_up_sync(0xffffffffu, c2w, 1);
                float r2 = __shfl_down_sync(0xffffffffu, c2x, 1);
                u64 mid1 = pk(c1y, c1z);
                u64 mid2 = pk(c2y, c2z);
                u64 t01_1 = mulx2(addx2(addx2(c01[0], c01[2]),
                                        addx2(pk(l1, c1x), mid1)), m01[1]);
                u64 t23_1 = mulx2(addx2(addx2(c23[0], c23[2]),
                                        addx2(mid1, pk(c1w, r1))), m23[1]);
                u64 t01_2 = mulx2(addx2(addx2(c01[1], c01[3]),
                                        addx2(pk(l2, c2x), mid2)), m01[2]);
                u64 t23_2 = mulx2(addx2(addx2(c23[1], c23[3]),
                                        addx2(mid2, pk(c2w, r2))), m23[2]);

                act_barrier();   // step-(s-1) stores now visible

                // ===== post-barrier: rows 0,3 (need smem) + edge fixups =====
                ulonglong2 uu = has_up ? *(const ulonglong2*)(cur + o0 - PITCH)
                                       : make_ulonglong2(0ull, 0ull);
                ulonglong2 dd = has_dn ? *(const ulonglong2*)(cur + o0 + 4 * PITCH)
                                       : make_ulonglong2(0ull, 0ull);

                float c0x, c0y, c0z, c0w, c3x, c3y, c3z, c3w;
                unpk(c01[0], c0x, c0y); unpk(c23[0], c0z, c0w);
                unpk(c01[3], c3x, c3y); unpk(c23[3], c3z, c3w);

                // row 0
                float l0 = __shfl_up_sync(0xffffffffu, c0w, 1);
                float r0v = __shfl_down_sync(0xffffffffu, c0x, 1);
                if (lane == 0  && rc0) l0  = cur[o0 - 1];
                if (lane == 31 && rc0) r0v = cur[o0 + 4];
                u64 mid0 = pk(c0y, c0z);
                u64 v01_0 = mulx2(addx2(addx2(uu.x, c01[1]),
                                        addx2(pk(l0, c0x), mid0)), m01[0]);
                u64 v23_0 = mulx2(addx2(addx2(uu.y, c23[1]),
                                        addx2(mid0, pk(c0w, r0v))), m23[0]);
                // row 3
                float l3 = __shfl_up_sync(0xffffffffu, c3w, 1);
                float r3 = __shfl_down_sync(0xffffffffu, c3x, 1);
                if (lane == 0  && rc3) l3 = cur[o0 + 3 * PITCH - 1];
                if (lane == 31 && rc3) r3 = cur[o0 + 3 * PITCH + 4];
                u64 mid3 = pk(c3y, c3z);
                u64 v01_3 = mulx2(addx2(addx2(c01[2], dd.x),
                                        addx2(pk(l3, c3x), mid3)), m01[3]);
                u64 v23_3 = mulx2(addx2(addx2(c23[2], dd.y),
                                        addx2(mid3, pk(c3w, r3))), m23[3]);

                // edge-lane horizontal fixups for precomputed rows 1,2
                if (lane == 0) {
                    if (rc1) {
                        float l = cur[o0 + PITCH - 1];
                        float mx, my; unpk(m01[1], mx, my);
                        float tl, th; unpk(t01_1, tl, th);
                        t01_1 = pk(mx * ((c0x + c2x) + (l + c1y)), th);
                    }
                    if (rc2) {
                        float l = cur[o0 + 2 * PITCH - 1];
                        float mx, my; unpk(m01[2], mx, my);
                        float tl, th; unpk(t01_2, tl, th);
                        t01_2 = pk(mx * ((c1x + c3x) + (l + c2y)), th);
                    }
                }
                if (lane == 31) {
                    if (rc1) {
                        float rr = cur[o0 + PITCH + 4];
                        float mz, mw; unpk(m23[1], mz, mw);
                        float tl, th; unpk(t23_1, tl, th);
                        t23_1 = pk(tl, mw * ((c0w + c2w) + (c1z + rr)));
                    }
                    if (rc2) {
                        float rr = cur[o0 + 2 * PITCH + 4];
                        float mz, mw; unpk(m23[2], mz, mw);
                        float tl, th; unpk(t23_2, tl, th);
                        t23_2 = pk(tl, mw * ((c1w + c3w) + (c2z + rr)));
                    }
                }

                // ===== commit + store =====
                if (rc0) { c01[0] = v01_0; c23[0] = v23_0;
                           *(ulonglong2*)(nxt + o0) = make_ulonglong2(v01_0, v23_0); }
                if (rc1) { c01[1] = t01_1; c23[1] = t23_1;
                           *(ulonglong2*)(nxt + o0 + PITCH) = make_ulonglong2(t01_1, t23_1); }
                if (rc2) { c01[2] = t01_2; c23[2] = t23_2;
                           *(ulonglong2*)(nxt + o0 + 2 * PITCH) = make_ulonglong2(t01_2, t23_2); }
                if (rc3) { c01[3] = v01_3; c23[3] = v23_3;
                           *(ulonglong2*)(nxt + o0 + 3 * PITCH) = make_ulonglong2(v01_3, v23_3); }

                float* t = cur; cur = nxt; nxt = t;
            }
        }
        // Rendezvous of all warps; also orders step-10 STS before write-back reads.
        __syncthreads();

        // ---- write interior (rows/cols [HALO, HALO+TILE)) from xs0 ----
        float* wb = (ss == NSS - 1) ? out : ((ss & 1) ? g_buf1 : g_buf0);
        for (int idx = tid; idx < TILE_H * TILE_W; idx += NTHREADS) {
            int r = HALO + (idx >> 7);
            int c = HALO + (idx & 127);
            wb[(r0b + r) * H + (c0 + c)] = xs0[r * PITCH + c];
        }
        if (ss == NSS - 1) break;

        grid_barrier(bid, ep0 + (unsigned)ss + 1u);

        // ---- refresh halo ring of xs0 from this super-step's buffer ----
        const float* rb = (ss & 1) ? g_buf1 : g_buf0;
        for (int i = tid; i < 2 * HALO * EXW; i += NTHREADS) {
            int r = i / EXW;
            int c = i - r * EXW;
            if (r >= HALO) r += TILE_H;
            int gr = r0b + r;
            int gc = c0 + c;
            float v = 0.f;
            if ((unsigned)gr < (unsigned)H && (unsigned)gc < (unsigned)H)
                v = rb[gr * H + gc];
            xs0[r * PITCH + c] = v;
        }
        for (int i = tid; i < TILE_H * 2 * HALO; i += NTHREADS) {
            int rr2 = i / (2 * HALO);
            int cc  = i - rr2 * (2 * HALO);
            int r = HALO + rr2;
            int c = (cc < HALO) ? cc : cc + TILE_W;
            int gr = r0b + r;
            int gc = c0 + c;
            float v = 0.f;
            if ((unsigned)gr < (unsigned)H && (unsigned)gc < (unsigned)H)
                v = rb[gr * H + gc];
            xs0[r * PITCH + c] = v;
        }
        __syncthreads();

        // ---- reload center registers from refreshed xs0 ----
        #pragma unroll
        for (int i = 0; i < 4; i++) {
            ulonglong2 v = *(const ulonglong2*)(xs0 + o0 + i * PITCH);
            c01[i] = v.x;
            c23[i] = v.y;
        }
        __syncthreads();
    }
}

extern "C" void kernel_launch(void* const* d_in, const int* in_sizes, int n_in,
                              void* d_out, int out_size) {
    (void)in_sizes; (void)n_in; (void)out_size;
    const float* X  = (const float*)d_in[0];
    const float* Y  = (const float*)d_in[1];
    const float* M1 = (const float*)d_in[2];   // Mask1: [1,1,1024,1024]
    float* out = (float*)d_out;

    cudaFuncSetAttribute(jacobi_persist, cudaFuncAttributeMaxDynamicSharedMemorySize,
                         SMEM_BYTES);

    dim3 grid(GRID_X, GRID_Y);   // (8, 16) = 128 CTAs, single wave on 148 SMs
    jacobi_persist<<<grid, NTHREADS, SMEM_BYTES>>>(X, Y, M1, out);
}